// round 9
// baseline (speedup 1.0000x reference)
#include <cuda_runtime.h>
#include <cuda_fp16.h>
#include <cstdint>

// ---------------------------------------------------------------------------
// CliffordEPModel collapsed:
//   pred[b,o] = sum_{ma} x[b,ma] * A[ma,o]                           (main MMA)
//   A[ma,o]   = c * sum_{hk} coef(a,k) * Win[h, m*8+(a^k)] * Wout[o, hk]
//   c = 1 - 0.9^20 ;  coef(a,k) = sgn(k,k)*sgn(a,a^k)  (Cl(3,0) Cayley)
// Both GEMMs: mma.sync m16n8k16 fp16 (fp32 accum), fragment-direct from
// global memory (no smem, no __syncthreads) for maximum latency tolerance.
// A k-permutation (positional 2c,2c+1,2c+8,2c+9 -> actual 4c..4c+3), applied
// identically to A and B operands, makes every fragment a contiguous load.
// ---------------------------------------------------------------------------

#define BATCH   8192
#define NSLICE  16                      // split-K for prep (hk slices of 256)
#define C_RELAX 0.8784233454094307f     // 1 - 0.9^20

// scratch
__device__ __align__(16) float g_P[NSLICE][64 * 512];   // prep partials [o][ma], 2 MB
__device__ __align__(16) uint4 g_Bpk[4096];             // packed fp16 B-frags, 64 KB

__device__ __forceinline__ float blade_sign(int a, int b) {
    int e = (b & 1) * (((a >> 1) & 1) + ((a >> 2) & 1)) + ((b >> 1) & 1) * ((a >> 2) & 1);
    return (e & 1) ? -1.0f : 1.0f;
}

__device__ __forceinline__ void mma_fp16(float* c, const uint32_t* a, uint32_t b0, uint32_t b1) {
    asm volatile(
        "mma.sync.aligned.m16n8k16.row.col.f32.f16.f16.f32 "
        "{%0,%1,%2,%3}, {%4,%5,%6,%7}, {%8,%9}, {%0,%1,%2,%3};"
        : "+f"(c[0]), "+f"(c[1]), "+f"(c[2]), "+f"(c[3])
        : "r"(a[0]), "r"(a[1]), "r"(a[2]), "r"(a[3]), "r"(b0), "r"(b1));
}

__device__ __forceinline__ uint32_t h2pack(float lo, float hi) {
    __half2 h = __floats2half2_rn(lo, hi);
    return *reinterpret_cast<uint32_t*>(&h);
}

// ---------------------------------------------------------------------------
// Kernel 1: prep GEMM, fragment-direct, barrier-free.
//   P[s][o, ma] = sum_{hk in slice s} Wout[o, hk] * coef(a,k)*Win[h, m8+(a^k)]
// 512 warps: warp = (ot in 4) x (mt in 8) x (s in 16); 16 o x 64 ma, K=256.
// A = Wout rows (row-major, contiguous float4 under pi).
// B = coef*Win gathered per-lane: float4 + XOR-butterfly + sign constants.
// ---------------------------------------------------------------------------
__global__ __launch_bounds__(64) void prep_kernel(
        const float* __restrict__ Win, const float* __restrict__ Wout) {
    int widx = blockIdx.x * 2 + (threadIdx.x >> 5);
    int l = threadIdx.x & 31;
    int s  = widx & 15;
    int mt = (widx >> 4) & 7;
    int ot = widx >> 7;

    int c  = l & 3;
    int rY = l >> 2;                 // A row-in-frag, also blade a for B lanes

    // lane constants for the B (coef*Win) gather
    int kb0 = (4 * c) & 7;           // blade index of slot j=0
    int a_bl = rY;
    int base_xor = a_bl ^ kb0;
    int perm = base_xor & 3;
    int colb = base_xor & ~3;
    float sg[4];
#pragma unroll
    for (int j = 0; j < 4; j++) {
        int kb = kb0 + j;
        sg[j] = blade_sign(kb, kb) * blade_sign(a_bl, a_bl ^ kb);
    }
    bool sw1 = perm & 1, sw2 = perm & 2;

    float acc[8][4];
#pragma unroll
    for (int nt = 0; nt < 8; nt++)
#pragma unroll
        for (int q = 0; q < 4; q++) acc[nt][q] = 0.f;

    const float* Wo0 = Wout + (ot * 16 + rY) * 4096 + 4 * c;
    const float* Wo1 = Wo0 + 8 * 4096;
    int hbump = (c >> 1);            // 4c >= 8 ?

#pragma unroll 4
    for (int t = 0; t < 16; t++) {
        int k0 = s * 256 + t * 16;
        // ---- A frags (Wout) ----
        float4 alo = *(const float4*)(Wo0 + k0);
        float4 ahi = *(const float4*)(Wo1 + k0);
        uint32_t A[4];
        A[0] = h2pack(alo.x, alo.y);
        A[1] = h2pack(ahi.x, ahi.y);
        A[2] = h2pack(alo.z, alo.w);
        A[3] = h2pack(ahi.z, ahi.w);

        int h = (k0 >> 3) + hbump;
        const float* wb = Win + h * 512 + mt * 64 + colb;
#pragma unroll
        for (int nt = 0; nt < 8; nt++) {
            float4 w = *(const float4*)(wb + nt * 8);
            float p0 = w.x, p1 = w.y, p2 = w.z, p3 = w.w;
            if (sw1) { float t0 = p0; p0 = p1; p1 = t0; t0 = p2; p2 = p3; p3 = t0; }
            if (sw2) { float t0 = p0; p0 = p2; p2 = t0; t0 = p1; p1 = p3; p3 = t0; }
            uint32_t b0 = h2pack(sg[0] * p0, sg[1] * p1);
            uint32_t b1 = h2pack(sg[2] * p2, sg[3] * p3);
            mma_fp16(acc[nt], A, b0, b1);
        }
    }

    // ---- epilogue: partial slab [o][ma] ----
    float* dst = g_P[s];
    int ro = ot * 16 + rY;
    int cb = mt * 64 + 2 * c;
#pragma unroll
    for (int nt = 0; nt < 8; nt++) {
        *(float2*)&dst[ro * 512 + cb + nt * 8]       = make_float2(acc[nt][0], acc[nt][1]);
        *(float2*)&dst[(ro + 8) * 512 + cb + nt * 8] = make_float2(acc[nt][2], acc[nt][3]);
    }
}

// ---------------------------------------------------------------------------
// Kernel 2: reduce split-K partials, *C_RELAX, fp16-cast, pack into main's
// B-fragment order (one uint4 per (chunk, nt, ks-pair, lane)).
// thread -> h2 unit (k-pair 2j, n): k runs over ma (=512), n over o (=64).
// ---------------------------------------------------------------------------
__global__ __launch_bounds__(256) void reduce_kernel() {
    int e = blockIdx.x * 256 + threadIdx.x;   // 0..16383
    int j = e & 255;                          // k-pair index (k = 2j)
    int n = e >> 8;                           // o

    float2 sum = make_float2(0.f, 0.f);
#pragma unroll
    for (int s = 0; s < NSLICE; s++) {
        float2 v = *(const float2*)&g_P[s][n * 512 + 2 * j];
        sum.x += v.x; sum.y += v.y;
    }
    uint32_t h = h2pack(sum.x * C_RELAX, sum.y * C_RELAX);

    int k   = 2 * j;
    int i   = k >> 6;                 // chunk
    int r   = k & 63;
    int ks  = r >> 4;
    int rem = r & 15;                 // even
    int cc  = rem >> 2;               // lane's c
    int comp = (ks & 1) * 2 + ((rem & 2) >> 1);
    int kp  = ks >> 1;
    int nt  = n >> 3;
    int lI  = ((n & 7) << 2) | cc;

    ((uint32_t*)g_Bpk)[((((i * 8 + nt) * 2 + kp) * 32) + lI) * 4 + comp] = h;
}

// ---------------------------------------------------------------------------
// Kernel 3: main GEMM, fragment-direct, barrier-free.
//   out(8192,64) = X(8192,512) @ A(512,64)
// 512 warps, each 16 rows x 64 cols, K=512 in 8 chunks.
// A-frags: float4 from X + cvt (pi-ordering). B-frags: uint4 from g_Bpk
// (64 KB, L1-resident after first chunk).
// ---------------------------------------------------------------------------
__global__ __launch_bounds__(64) void main_kernel(
        const float* __restrict__ X, float* __restrict__ out) {
    int W = blockIdx.x * 2 + (threadIdx.x >> 5);
    int l = threadIdx.x & 31;
    int c = l & 3, rY = l >> 2;
    int r0 = W * 16;

    float acc[8][4];
#pragma unroll
    for (int nt = 0; nt < 8; nt++)
#pragma unroll
        for (int q = 0; q < 4; q++) acc[nt][q] = 0.f;

    const float* x0 = X + (r0 + rY) * 512 + 4 * c;
    const float* x1 = x0 + 8 * 512;

#pragma unroll
    for (int i = 0; i < 8; i++) {
        int k0 = i * 64;
        uint32_t A[4][4];
#pragma unroll
        for (int ks = 0; ks < 4; ks++) {
            float4 lo = *(const float4*)(x0 + k0 + ks * 16);
            float4 hi = *(const float4*)(x1 + k0 + ks * 16);
            A[ks][0] = h2pack(lo.x, lo.y);
            A[ks][1] = h2pack(hi.x, hi.y);
            A[ks][2] = h2pack(lo.z, lo.w);
            A[ks][3] = h2pack(hi.z, hi.w);
        }
#pragma unroll
        for (int nt = 0; nt < 8; nt++) {
#pragma unroll
            for (int kp = 0; kp < 2; kp++) {
                uint4 b = g_Bpk[((i * 8 + nt) * 2 + kp) * 32 + l];
                mma_fp16(acc[nt], A[2 * kp],     b.x, b.y);
                mma_fp16(acc[nt], A[2 * kp + 1], b.z, b.w);
            }
        }
    }

    int rr = r0 + rY;
    int cb = 2 * c;
#pragma unroll
    for (int nt = 0; nt < 8; nt++) {
        *(float2*)&out[rr * 64 + nt * 8 + cb]       = make_float2(acc[nt][0], acc[nt][1]);
        *(float2*)&out[(rr + 8) * 64 + nt * 8 + cb] = make_float2(acc[nt][2], acc[nt][3]);
    }
}

// ---------------------------------------------------------------------------
extern "C" void kernel_launch(void* const* d_in, const int* in_sizes, int n_in,
                              void* d_out, int out_size) {
    const float* x    = (const float*)d_in[0];   // (8192, 512)
    const float* Win  = (const float*)d_in[1];   // (512h, 512mb)
    const float* Wout = (const float*)d_in[2];   // (64, 4096)
    float* out        = (float*)d_out;           // (8192, 64)

    prep_kernel<<<256, 64>>>(Win, Wout);
    reduce_kernel<<<64, 256>>>();
    main_kernel<<<256, 64>>>(x, out);
}

// round 10
// speedup vs baseline: 1.2771x; 1.2771x over previous
#include <cuda_runtime.h>
#include <cuda_fp16.h>
#include <cstdint>

// ---------------------------------------------------------------------------
// CliffordEPModel collapsed:
//   pred[b,o] = sum_{ma} x[b,ma] * A[ma,o]                           (main MMA)
//   A[ma,o]   = c * sum_{hk} coef(a,k) * Win[h, m*8+(a^k)] * Wout[o, hk]
//   c = 1 - 0.9^20 ;  coef(a,k) = sgn(k,k)*sgn(a,a^k)  (Cl(3,0) Cayley)
// Both GEMMs mma.sync m16n8k16 fp16 (fp32 accum).
// prep: smem-staged (Cayley signs folded once), 256 CTAs -> 4 CTAs/SM.
// main: fragment-direct from global (no smem/syncs), 1024 warps.
// ---------------------------------------------------------------------------

#define BATCH   8192
#define NSLICE  16                      // split-K for prep (hk slices of 256)
#define C_RELAX 0.8784233454094307f     // 1 - 0.9^20

// scratch
__device__ __align__(16) float g_P[NSLICE][64 * 512];   // prep partials [o][ma], 2 MB
__device__ __align__(16) uint4 g_Bpk[4096];             // packed fp16 B-frags, 64 KB

__device__ __forceinline__ float blade_sign(int a, int b) {
    int e = (b & 1) * (((a >> 1) & 1) + ((a >> 2) & 1)) + ((b >> 1) & 1) * ((a >> 2) & 1);
    return (e & 1) ? -1.0f : 1.0f;
}

__device__ __forceinline__ uint32_t smem_u32(const void* p) {
    uint32_t a;
    asm("{ .reg .u64 t; cvta.to.shared.u64 t, %1; cvt.u32.u64 %0, t; }" : "=r"(a) : "l"(p));
    return a;
}

__device__ __forceinline__ void ldsm_x4(uint32_t* r, uint32_t addr) {
    asm volatile("ldmatrix.sync.aligned.m8n8.x4.shared.b16 {%0,%1,%2,%3}, [%4];"
                 : "=r"(r[0]), "=r"(r[1]), "=r"(r[2]), "=r"(r[3]) : "r"(addr));
}

__device__ __forceinline__ void mma_fp16(float* c, const uint32_t* a, uint32_t b0, uint32_t b1) {
    asm volatile(
        "mma.sync.aligned.m16n8k16.row.col.f32.f16.f16.f32 "
        "{%0,%1,%2,%3}, {%4,%5,%6,%7}, {%8,%9}, {%0,%1,%2,%3};"
        : "+f"(c[0]), "+f"(c[1]), "+f"(c[2]), "+f"(c[3])
        : "r"(a[0]), "r"(a[1]), "r"(a[2]), "r"(a[3]), "r"(b0), "r"(b1));
}

__device__ __forceinline__ uint32_t h2pack(float lo, float hi) {
    __half2 h = __floats2half2_rn(lo, hi);
    return *reinterpret_cast<uint32_t*>(&h);
}

// ---------------------------------------------------------------------------
// Kernel 1: prep GEMM (smem-staged, split-K).
//   P[s][o, ma] = sum_{hk in slice s} coef(a,k)*Win[h, m8+(a^k)] * Wout[o, hk]
// grid (8 ma-tiles, 2 o-tiles, 16 slices) = 256 CTAs, 256 threads.
// Per CTA: 64 ma x 32 o, K = 256 (32 h). smem 50.7 KB -> 4 CTAs/SM.
// A tile: Cayley XOR gather + signs folded at staging. B tile: Wout rows.
// Row pitch 528 B -> conflict-free ldmatrix.
// ---------------------------------------------------------------------------
#define P_ROW    528
#define P_AS     0
#define P_BS     (64 * P_ROW)
#define PREP_SMEM (96 * P_ROW)          // 50688

__global__ __launch_bounds__(256) void prep_gemm_kernel(
        const float* __restrict__ Win, const float* __restrict__ Wout) {
    extern __shared__ char sm[];
    int tid = threadIdx.x;
    int w   = tid >> 5, l = tid & 31;
    int ma0 = blockIdx.x * 64;
    int ob0 = blockIdx.y * 32;
    int s   = blockIdx.z;               // hk slice (256 wide = 32 h)

    // ---- stage A tile (Cayley-gathered Win): thread = (m_local, h_local) ----
    {
        int m_local = tid & 7;
        int h_local = tid >> 3;         // 0..31
        int h  = s * 32 + h_local;
        int mg = blockIdx.x * 8 + m_local;
        float w8[8];
        float4 w0 = *(const float4*)&Win[h * 512 + mg * 8];
        float4 w1 = *(const float4*)&Win[h * 512 + mg * 8 + 4];
        w8[0] = w0.x; w8[1] = w0.y; w8[2] = w0.z; w8[3] = w0.w;
        w8[4] = w1.x; w8[5] = w1.y; w8[6] = w1.z; w8[7] = w1.w;
#pragma unroll
        for (int a = 0; a < 8; a++) {
            __half hv[8];
#pragma unroll
            for (int k = 0; k < 8; k++) {
                float coef = blade_sign(k, k) * blade_sign(a, a ^ k);
                hv[k] = __float2half_rn(coef * w8[a ^ k]);
            }
            *(uint4*)(sm + P_AS + (m_local * 8 + a) * P_ROW + h_local * 16) =
                *reinterpret_cast<uint4*>(hv);
        }
    }
    // ---- stage B tile: Bs[o][j] = fp16(Wout[ob0+o, s*256 + j]) ----
    {
        int o  = tid >> 3;              // 0..31
        int j0 = (tid & 7) * 32;
        const float* src = &Wout[(ob0 + o) * 4096 + s * 256 + j0];
#pragma unroll
        for (int jj = 0; jj < 32; jj += 8) {
            float4 v0 = *(const float4*)&src[jj];
            float4 v1 = *(const float4*)&src[jj + 4];
            uint4 pk = make_uint4(h2pack(v0.x, v0.y), h2pack(v0.z, v0.w),
                                  h2pack(v1.x, v1.y), h2pack(v1.z, v1.w));
            *(uint4*)(sm + P_BS + o * P_ROW + (j0 + jj) * 2) = pk;
        }
    }
    __syncthreads();

    // ---- compute: 8 warps = 4 m-groups x 2 n-groups; K=256 in 4 chunks ----
    int mg = w & 3, ng = w >> 2;
    int grp = l >> 3, rin = l & 7;
    uint32_t smb = smem_u32(sm);
    uint32_t aB  = smb + P_AS + (uint32_t)((mg * 16 + rin + (grp & 1) * 8) * P_ROW + (grp >> 1) * 16);
    uint32_t bB0 = smb + P_BS + (uint32_t)((ng * 16 + rin) * P_ROW + grp * 16);

    float acc[2][4];
#pragma unroll
    for (int t = 0; t < 2; t++)
#pragma unroll
        for (int q = 0; q < 4; q++) acc[t][q] = 0.f;

#pragma unroll
    for (int c = 0; c < 4; c++) {
        uint32_t Af[4][4];
#pragma unroll
        for (int ks = 0; ks < 4; ks++) ldsm_x4(Af[ks], aB + c * 128 + ks * 32);
#pragma unroll
        for (int t = 0; t < 2; t++) {
            uint32_t bf[8];
            uint32_t bB = bB0 + (uint32_t)(t * 8 * P_ROW + c * 128);
#pragma unroll
            for (int kp = 0; kp < 2; kp++) ldsm_x4(&bf[kp * 4], bB + kp * 64);
#pragma unroll
            for (int ks = 0; ks < 4; ks++)
                mma_fp16(acc[t], Af[ks], bf[ks * 2], bf[ks * 2 + 1]);
        }
    }

    // ---- epilogue: partial slab, [o][ma] layout ----
    float* dst = g_P[s];
    int ma_r = ma0 + mg * 16 + (l >> 2);
    int o_c  = ob0 + ng * 16 + (l & 3) * 2;
#pragma unroll
    for (int t = 0; t < 2; t++) {
        int o0 = o_c + t * 8;
        dst[o0 * 512 + ma_r]           = acc[t][0];
        dst[(o0 + 1) * 512 + ma_r]     = acc[t][1];
        dst[o0 * 512 + ma_r + 8]       = acc[t][2];
        dst[(o0 + 1) * 512 + ma_r + 8] = acc[t][3];
    }
}

// ---------------------------------------------------------------------------
// Kernel 2: reduce split-K partials, *C_RELAX, fp16-cast, pack into main's
// B-fragment order (one uint4 per (chunk, nt, ks-pair, lane)).
// ---------------------------------------------------------------------------
__global__ __launch_bounds__(256) void reduce_kernel() {
    int e = blockIdx.x * 256 + threadIdx.x;   // 0..16383
    int j = e & 255;                          // k-pair index (k = 2j over ma)
    int n = e >> 8;                           // o

    float2 sum = make_float2(0.f, 0.f);
#pragma unroll
    for (int s = 0; s < NSLICE; s++) {
        float2 v = *(const float2*)&g_P[s][n * 512 + 2 * j];
        sum.x += v.x; sum.y += v.y;
    }
    uint32_t h = h2pack(sum.x * C_RELAX, sum.y * C_RELAX);

    int k   = 2 * j;
    int i   = k >> 6;                 // chunk
    int r   = k & 63;
    int ks  = r >> 4;
    int rem = r & 15;                 // even
    int cc  = rem >> 2;               // lane's c
    int comp = (ks & 1) * 2 + ((rem & 2) >> 1);
    int kp  = ks >> 1;
    int nt  = n >> 3;
    int lI  = ((n & 7) << 2) | cc;

    ((uint32_t*)g_Bpk)[((((i * 8 + nt) * 2 + kp) * 32) + lI) * 4 + comp] = h;
}

// ---------------------------------------------------------------------------
// Kernel 3: main GEMM, fragment-direct, barrier-free.
//   out(8192,64) = X(8192,512) @ A(512,64)
// 1024 warps (256 blocks x 4): warp = 16 rows x 32 cols, K=512 in 8 chunks.
// Block: 2 row-groups x 2 col-halves (col-halves share X rows -> L1 hits).
// A-frags: float4 from X + cvt. B-frags: uint4 from g_Bpk (64 KB, L1-hot).
// ---------------------------------------------------------------------------
__global__ __launch_bounds__(128) void main_kernel(
        const float* __restrict__ X, float* __restrict__ out) {
    int w  = threadIdx.x >> 5;        // 0..3
    int l  = threadIdx.x & 31;
    int r0 = blockIdx.x * 32 + (w & 1) * 16;
    int ch = w >> 1;                  // col half (32 cols)
    int c  = l & 3, rY = l >> 2;

    float acc[4][4];
#pragma unroll
    for (int nt = 0; nt < 4; nt++)
#pragma unroll
        for (int q = 0; q < 4; q++) acc[nt][q] = 0.f;

    const float* x0 = X + (r0 + rY) * 512 + 4 * c;
    const float* x1 = x0 + 8 * 512;

#pragma unroll
    for (int i = 0; i < 8; i++) {
        int k0 = i * 64;
        uint32_t A[4][4];
#pragma unroll
        for (int ks = 0; ks < 4; ks++) {
            float4 lo = *(const float4*)(x0 + k0 + ks * 16);
            float4 hi = *(const float4*)(x1 + k0 + ks * 16);
            A[ks][0] = h2pack(lo.x, lo.y);
            A[ks][1] = h2pack(hi.x, hi.y);
            A[ks][2] = h2pack(lo.z, lo.w);
            A[ks][3] = h2pack(hi.z, hi.w);
        }
#pragma unroll
        for (int nt = 0; nt < 4; nt++) {
            int ntg = ch * 4 + nt;
#pragma unroll
            for (int kp = 0; kp < 2; kp++) {
                uint4 b = g_Bpk[((i * 8 + ntg) * 2 + kp) * 32 + l];
                mma_fp16(acc[nt], A[2 * kp],     b.x, b.y);
                mma_fp16(acc[nt], A[2 * kp + 1], b.z, b.w);
            }
        }
    }

    int rr = r0 + rY;
    int cb = ch * 32 + 2 * c;
#pragma unroll
    for (int nt = 0; nt < 4; nt++) {
        *(float2*)&out[rr * 64 + cb + nt * 8]       = make_float2(acc[nt][0], acc[nt][1]);
        *(float2*)&out[(rr + 8) * 64 + cb + nt * 8] = make_float2(acc[nt][2], acc[nt][3]);
    }
}

// ---------------------------------------------------------------------------
extern "C" void kernel_launch(void* const* d_in, const int* in_sizes, int n_in,
                              void* d_out, int out_size) {
    const float* x    = (const float*)d_in[0];   // (8192, 512)
    const float* Win  = (const float*)d_in[1];   // (512h, 512mb)
    const float* Wout = (const float*)d_in[2];   // (64, 4096)
    float* out        = (float*)d_out;           // (8192, 64)

    cudaFuncSetAttribute(prep_gemm_kernel,
                         cudaFuncAttributeMaxDynamicSharedMemorySize, PREP_SMEM);

    prep_gemm_kernel<<<dim3(8, 2, NSLICE), 256, PREP_SMEM>>>(Win, Wout);
    reduce_kernel<<<64, 256>>>();
    main_kernel<<<256, 128>>>(x, out);
}

// round 12
// speedup vs baseline: 1.3947x; 1.0921x over previous
#include <cuda_runtime.h>
#include <cuda_fp16.h>
#include <cstdint>

// ---------------------------------------------------------------------------
// CliffordEPModel collapsed:
//   pred[b,o] = sum_{ma} x[b,ma] * A[ma,o]                           (main MMA)
//   A[ma,o]   = c * sum_{hk} coef(a,k) * Win[h, m*8+(a^k)] * Wout[o, hk]
//   c = 1 - 0.9^20 ;  coef(a,k) = sgn(k,k)*sgn(a,a^k)  (Cl(3,0) Cayley)
// Both GEMMs mma.sync m16n8k16 fp16 (fp32 accum).
// This round: wavefront-count optimization — every LDG/STG pattern chosen to
// touch <= 8 cache lines per instruction (prior prep B-staging touched 32).
// ---------------------------------------------------------------------------

#define BATCH   8192
#define NSLICE  16                      // split-K for prep (hk slices of 256)
#define C_RELAX 0.8784233454094307f     // 1 - 0.9^20

// scratch
__device__ __align__(16) float g_P[NSLICE][512 * 64];   // prep partials [ma][o], 2 MB
__device__ __align__(16) uint4 g_Bpk[4096];             // packed fp16 B-frags, 64 KB

__device__ __forceinline__ float blade_sign(int a, int b) {
    int e = (b & 1) * (((a >> 1) & 1) + ((a >> 2) & 1)) + ((b >> 1) & 1) * ((a >> 2) & 1);
    return (e & 1) ? -1.0f : 1.0f;
}

__device__ __forceinline__ uint32_t smem_u32(const void* p) {
    uint32_t a;
    asm("{ .reg .u64 t; cvta.to.shared.u64 t, %1; cvt.u32.u64 %0, t; }" : "=r"(a) : "l"(p));
    return a;
}

__device__ __forceinline__ void ldsm_x4(uint32_t* r, uint32_t addr) {
    asm volatile("ldmatrix.sync.aligned.m8n8.x4.shared.b16 {%0,%1,%2,%3}, [%4];"
                 : "=r"(r[0]), "=r"(r[1]), "=r"(r[2]), "=r"(r[3]) : "r"(addr));
}

__device__ __forceinline__ void mma_fp16(float* c, const uint32_t* a, uint32_t b0, uint32_t b1) {
    asm volatile(
        "mma.sync.aligned.m16n8k16.row.col.f32.f16.f16.f32 "
        "{%0,%1,%2,%3}, {%4,%5,%6,%7}, {%8,%9}, {%0,%1,%2,%3};"
        : "+f"(c[0]), "+f"(c[1]), "+f"(c[2]), "+f"(c[3])
        : "r"(a[0]), "r"(a[1]), "r"(a[2]), "r"(a[3]), "r"(b0), "r"(b1));
}

__device__ __forceinline__ uint32_t h2pack(float lo, float hi) {
    __half2 h = __floats2half2_rn(lo, hi);
    return *reinterpret_cast<uint32_t*>(&h);
}

// ---------------------------------------------------------------------------
// Kernel 1: prep GEMM (smem-staged, split-K).
//   P[s][ma, o] = sum_{hk in slice s} coef(a,k)*Win[h, m8+(a^k)] * Wout[o, hk]
// grid (8 ma-tiles, 2 o-tiles, 16 slices) = 256 CTAs, 256 threads.
// Per CTA: 64 ma x 32 o, K = 256. smem 50.7 KB -> 4 CTAs/SM (32 warps/SM).
// B staged with a LINEAR coalesced map (4 lines/LDG). A staged with the
// Cayley XOR gather + signs (8 lines/LDG). Row pitch 528 B.
// ---------------------------------------------------------------------------
#define P_ROW    528
#define P_AS     0
#define P_BS     (64 * P_ROW)
#define PREP_SMEM (96 * P_ROW)          // 50688

__global__ __launch_bounds__(256) void prep_gemm_kernel(
        const float* __restrict__ Win, const float* __restrict__ Wout) {
    extern __shared__ char sm[];
    int tid = threadIdx.x;
    int w   = tid >> 5, l = tid & 31;
    int ma0 = blockIdx.x * 64;
    int ob0 = blockIdx.y * 32;
    int s   = blockIdx.z;               // hk slice (256 wide = 32 h)

    // ---- stage B tile, coalesced: 32 o-rows x 256 floats -> fp16 ----
#pragma unroll
    for (int it = 0; it < 8; it++) {
        int idx = it * 256 + tid;       // 0..2047 (float4 units)
        int row = idx >> 6;             // o-local 0..31
        int c4  = idx & 63;             // float4 within row
        float4 v = *(const float4*)&Wout[(ob0 + row) * 4096 + s * 256 + c4 * 4];
        uint2 pk = make_uint2(h2pack(v.x, v.y), h2pack(v.z, v.w));
        *(uint2*)(sm + P_BS + row * P_ROW + c4 * 8) = pk;
    }

    // ---- stage A tile (Cayley-gathered Win): thread = (m_local, h_local) ----
    {
        int m_local = tid & 7;
        int h_local = tid >> 3;         // 0..31
        int h  = s * 32 + h_local;
        int mg = blockIdx.x * 8 + m_local;
        float w8[8];
        float4 w0 = *(const float4*)&Win[h * 512 + mg * 8];
        float4 w1 = *(const float4*)&Win[h * 512 + mg * 8 + 4];
        w8[0] = w0.x; w8[1] = w0.y; w8[2] = w0.z; w8[3] = w0.w;
        w8[4] = w1.x; w8[5] = w1.y; w8[6] = w1.z; w8[7] = w1.w;
#pragma unroll
        for (int a = 0; a < 8; a++) {
            __half hv[8];
#pragma unroll
            for (int k = 0; k < 8; k++) {
                float coef = blade_sign(k, k) * blade_sign(a, a ^ k);
                hv[k] = __float2half_rn(coef * w8[a ^ k]);
            }
            *(uint4*)(sm + P_AS + (m_local * 8 + a) * P_ROW + h_local * 16) =
                *reinterpret_cast<uint4*>(hv);
        }
    }
    __syncthreads();

    // ---- compute: 8 warps = 4 m-groups x 2 n-groups; K=256 in 4 chunks ----
    int mg = w & 3, ng = w >> 2;
    int grp = l >> 3, rin = l & 7;
    uint32_t smb = smem_u32(sm);
    uint32_t aB  = smb + P_AS + (uint32_t)((mg * 16 + rin + (grp & 1) * 8) * P_ROW + (grp >> 1) * 16);
    uint32_t bB0 = smb + P_BS + (uint32_t)((ng * 16 + rin) * P_ROW + grp * 16);

    float acc[2][4];
#pragma unroll
    for (int t = 0; t < 2; t++)
#pragma unroll
        for (int q = 0; q < 4; q++) acc[t][q] = 0.f;

#pragma unroll
    for (int c = 0; c < 4; c++) {
        uint32_t Af[4][4];
#pragma unroll
        for (int ks = 0; ks < 4; ks++) ldsm_x4(Af[ks], aB + c * 128 + ks * 32);
#pragma unroll
        for (int t = 0; t < 2; t++) {
            uint32_t bf[8];
            uint32_t bB = bB0 + (uint32_t)(t * 8 * P_ROW + c * 128);
#pragma unroll
            for (int kp = 0; kp < 2; kp++) ldsm_x4(&bf[kp * 4], bB + kp * 64);
#pragma unroll
            for (int ks = 0; ks < 4; ks++)
                mma_fp16(acc[t], Af[ks], bf[ks * 2], bf[ks * 2 + 1]);
        }
    }

    // ---- epilogue: partial slab, [ma][o] layout, float2 stores ----
    float* dst = g_P[s];
    int ma_r = ma0 + mg * 16 + (l >> 2);
    int o_c  = ob0 + ng * 16 + (l & 3) * 2;
#pragma unroll
    for (int t = 0; t < 2; t++) {
        *(float2*)&dst[ma_r * 64 + o_c + t * 8]       = make_float2(acc[t][0], acc[t][1]);
        *(float2*)&dst[(ma_r + 8) * 64 + o_c + t * 8] = make_float2(acc[t][2], acc[t][3]);
    }
}

// ---------------------------------------------------------------------------
// Kernel 2: reduce split-K partials, *C_RELAX, fp16-cast, pack into main's
// B-fragment order. thread e -> (j = e>>6 over ma-pairs, o = e&63);
// loads are lane-coalesced over o (1 line per warp-load).
// ---------------------------------------------------------------------------
__global__ __launch_bounds__(256) void reduce_kernel() {
    int e = blockIdx.x * 256 + threadIdx.x;   // 0..16383
    int o = e & 63;
    int j = e >> 6;                           // k-pair index (k = 2j over ma)

    float s0 = 0.f, s1 = 0.f;
#pragma unroll
    for (int s = 0; s < NSLICE; s++) {
        s0 += g_P[s][(2 * j) * 64 + o];
        s1 += g_P[s][(2 * j + 1) * 64 + o];
    }
    uint32_t h = h2pack(s0 * C_RELAX, s1 * C_RELAX);

    int k   = 2 * j;
    int n   = o;
    int i   = k >> 6;                 // chunk
    int r   = k & 63;
    int ks  = r >> 4;
    int rem = r & 15;                 // even
    int cc  = rem >> 2;               // lane's c
    int comp = (ks & 1) * 2 + ((rem & 2) >> 1);
    int kp  = ks >> 1;
    int nt  = n >> 3;
    int lI  = ((n & 7) << 2) | cc;

    ((uint32_t*)g_Bpk)[((((i * 8 + nt) * 2 + kp) * 32) + lI) * 4 + comp] = h;
}

// ---------------------------------------------------------------------------
// Kernel 3: main GEMM, fragment-direct with K-split-2 smem combine.
//   out(8192,64) = X(8192,512) @ A(512,64)
// 256 blocks x 128 threads = 1024 warps. Block = 2 row-groups x 2 k-halves.
// Warp = 16 rows x 64 cols x K=256 (4 chunks). Each X chunk-row is loaded by
// exactly ONE warp (keeps total wavefronts at the R9 level while doubling
// warps-in-flight). k-half-1 dumps acc to smem; k-half-0 combines + stores.
// ---------------------------------------------------------------------------
__global__ __launch_bounds__(128) void main_kernel(
        const float* __restrict__ X, float* __restrict__ out) {
    __shared__ float red[2][8][32][4];   // 8 KB
    int w  = threadIdx.x >> 5;           // 0..3
    int l  = threadIdx.x & 31;
    int rg = w & 1;                      // row-group within block
    int kh = w >> 1;                     // k-half
    int r0 = blockIdx.x * 32 + rg * 16;
    int c  = l & 3, rY = l >> 2;

    float acc[8][4];
#pragma unroll
    for (int nt = 0; nt < 8; nt++)
#pragma unroll
        for (int q = 0; q < 4; q++) acc[nt][q] = 0.f;

    const float* x0 = X + (r0 + rY) * 512 + 4 * c;
    const float* x1 = x0 + 8 * 512;

#pragma unroll
    for (int ii = 0; ii < 4; ii++) {
        int i  = kh * 4 + ii;
        int k0 = i * 64;
        uint32_t A[4][4];
#pragma unroll
        for (int ks = 0; ks < 4; ks++) {
            float4 lo = *(const float4*)(x0 + k0 + ks * 16);
            float4 hi = *(const float4*)(x1 + k0 + ks * 16);
            A[ks][0] = h2pack(lo.x, lo.y);
            A[ks][1] = h2pack(hi.x, hi.y);
            A[ks][2] = h2pack(lo.z, lo.w);
            A[ks][3] = h2pack(hi.z, hi.w);
        }
#pragma unroll
        for (int nt = 0; nt < 8; nt++) {
#pragma unroll
            for (int kp = 0; kp < 2; kp++) {
                uint4 b = g_Bpk[((i * 8 + nt) * 2 + kp) * 32 + l];
                mma_fp16(acc[nt], A[2 * kp],     b.x, b.y);
                mma_fp16(acc[nt], A[2 * kp + 1], b.z, b.w);
            }
        }
    }

    if (kh == 1) {
#pragma unroll
        for (int nt = 0; nt < 8; nt++)
            *(float4*)&red[rg][nt][l][0] = *(float4*)acc[nt];
    }
    __syncthreads();
    if (kh == 0) {
        int rr = r0 + rY;
        int cb = 2 * c;
#pragma unroll
        for (int nt = 0; nt < 8; nt++) {
            float4 v = *(float4*)&red[rg][nt][l][0];
            acc[nt][0] += v.x; acc[nt][1] += v.y;
            acc[nt][2] += v.z; acc[nt][3] += v.w;
            *(float2*)&out[rr * 64 + nt * 8 + cb]       = make_float2(acc[nt][0], acc[nt][1]);
            *(float2*)&out[(rr + 8) * 64 + nt * 8 + cb] = make_float2(acc[nt][2], acc[nt][3]);
        }
    }
}

// ---------------------------------------------------------------------------
extern "C" void kernel_launch(void* const* d_in, const int* in_sizes, int n_in,
                              void* d_out, int out_size) {
    const float* x    = (const float*)d_in[0];   // (8192, 512)
    const float* Win  = (const float*)d_in[1];   // (512h, 512mb)
    const float* Wout = (const float*)d_in[2];   // (64, 4096)
    float* out        = (float*)d_out;           // (8192, 64)

    cudaFuncSetAttribute(prep_gemm_kernel,
                         cudaFuncAttributeMaxDynamicSharedMemorySize, PREP_SMEM);

    prep_gemm_kernel<<<dim3(8, 2, NSLICE), 256, PREP_SMEM>>>(Win, Wout);
    reduce_kernel<<<64, 256>>>();
    main_kernel<<<256, 128>>>(x, out);
}

// round 13
// speedup vs baseline: 1.6091x; 1.1537x over previous
#include <cuda_runtime.h>
#include <cuda_fp16.h>
#include <cstdint>

// ---------------------------------------------------------------------------
// CliffordEPModel collapsed:
//   pred[b,o] = sum_{ma} x[b,ma] * A[ma,o]                           (main MMA)
//   A[ma,o]   = c * sum_{hk} coef(a,k) * Win[h, m*8+(a^k)] * Wout[o, hk]
//   c = 1 - 0.9^20 ;  coef(a,k) = sgn(k,k)*sgn(a,a^k)  (Cl(3,0) Cayley)
// Both GEMMs mma.sync m16n8k16 fp16 (fp32 accum).
// This round: memory-level-parallelism fixes — batch ALL global loads into
// registers before any dependent op (prep staging was serializing at MLP~1),
// and software-pipeline main's X loads across the MMA block.
// ---------------------------------------------------------------------------

#define BATCH   8192
#define NSLICE  16                      // split-K for prep (hk slices of 256)
#define C_RELAX 0.8784233454094307f     // 1 - 0.9^20

// scratch
__device__ __align__(16) float g_P[NSLICE][512 * 64];   // prep partials [ma][o], 2 MB
__device__ __align__(16) uint4 g_Bpk[4096];             // packed fp16 B-frags, 64 KB

__device__ __forceinline__ float blade_sign(int a, int b) {
    int e = (b & 1) * (((a >> 1) & 1) + ((a >> 2) & 1)) + ((b >> 1) & 1) * ((a >> 2) & 1);
    return (e & 1) ? -1.0f : 1.0f;
}

__device__ __forceinline__ uint32_t smem_u32(const void* p) {
    uint32_t a;
    asm("{ .reg .u64 t; cvta.to.shared.u64 t, %1; cvt.u32.u64 %0, t; }" : "=r"(a) : "l"(p));
    return a;
}

__device__ __forceinline__ void ldsm_x4(uint32_t* r, uint32_t addr) {
    asm volatile("ldmatrix.sync.aligned.m8n8.x4.shared.b16 {%0,%1,%2,%3}, [%4];"
                 : "=r"(r[0]), "=r"(r[1]), "=r"(r[2]), "=r"(r[3]) : "r"(addr));
}

__device__ __forceinline__ void mma_fp16(float* c, const uint32_t* a, uint32_t b0, uint32_t b1) {
    asm volatile(
        "mma.sync.aligned.m16n8k16.row.col.f32.f16.f16.f32 "
        "{%0,%1,%2,%3}, {%4,%5,%6,%7}, {%8,%9}, {%0,%1,%2,%3};"
        : "+f"(c[0]), "+f"(c[1]), "+f"(c[2]), "+f"(c[3])
        : "r"(a[0]), "r"(a[1]), "r"(a[2]), "r"(a[3]), "r"(b0), "r"(b1));
}

__device__ __forceinline__ uint32_t h2pack(float lo, float hi) {
    __half2 h = __floats2half2_rn(lo, hi);
    return *reinterpret_cast<uint32_t*>(&h);
}

// ---------------------------------------------------------------------------
// Kernel 1: prep GEMM (smem-staged, split-K).
//   P[s][ma, o] = sum_{hk in slice s} coef(a,k)*Win[h, m8+(a^k)] * Wout[o, hk]
// grid (8 ma-tiles, 2 o-tiles, 16 slices) = 256 CTAs, 256 threads.
// ALL 10 global loads per thread are issued before any conversion/store
// (MLP=10); __launch_bounds__(256,1) gives ptxas register headroom.
// ---------------------------------------------------------------------------
#define P_ROW    528
#define P_AS     0
#define P_BS     (64 * P_ROW)
#define PREP_SMEM (96 * P_ROW)          // 50688

__global__ __launch_bounds__(256, 1) void prep_gemm_kernel(
        const float* __restrict__ Win, const float* __restrict__ Wout) {
    extern __shared__ char sm[];
    int tid = threadIdx.x;
    int w   = tid >> 5, l = tid & 31;
    int ma0 = blockIdx.x * 64;
    int ob0 = blockIdx.y * 32;
    int s   = blockIdx.z;               // hk slice (256 wide = 32 h)

    // ======== issue ALL global loads first (MLP = 10) ========
    float4 bv[8];
#pragma unroll
    for (int it = 0; it < 8; it++) {
        int idx = it * 256 + tid;       // float4 units
        int row = idx >> 6;             // o-local 0..31
        int c4  = idx & 63;
        bv[it] = *(const float4*)&Wout[(ob0 + row) * 4096 + s * 256 + c4 * 4];
    }
    int m_local = tid & 7;
    int h_local = tid >> 3;             // 0..31
    int h  = s * 32 + h_local;
    int mg = blockIdx.x * 8 + m_local;
    float4 w0 = *(const float4*)&Win[h * 512 + mg * 8];
    float4 w1 = *(const float4*)&Win[h * 512 + mg * 8 + 4];

    // ======== convert + store B tile ========
#pragma unroll
    for (int it = 0; it < 8; it++) {
        int idx = it * 256 + tid;
        int row = idx >> 6;
        int c4  = idx & 63;
        uint2 pk = make_uint2(h2pack(bv[it].x, bv[it].y), h2pack(bv[it].z, bv[it].w));
        *(uint2*)(sm + P_BS + row * P_ROW + c4 * 8) = pk;
    }
    // ======== convert + store A tile (Cayley gather + signs) ========
    {
        float w8[8] = {w0.x, w0.y, w0.z, w0.w, w1.x, w1.y, w1.z, w1.w};
#pragma unroll
        for (int a = 0; a < 8; a++) {
            __half hv[8];
#pragma unroll
            for (int k = 0; k < 8; k++) {
                float coef = blade_sign(k, k) * blade_sign(a, a ^ k);
                hv[k] = __float2half_rn(coef * w8[a ^ k]);
            }
            *(uint4*)(sm + P_AS + (m_local * 8 + a) * P_ROW + h_local * 16) =
                *reinterpret_cast<uint4*>(hv);
        }
    }
    __syncthreads();

    // ---- compute: 8 warps = 4 m-groups x 2 n-groups; K=256 in 4 chunks ----
    int mg2 = w & 3, ng = w >> 2;
    int grp = l >> 3, rin = l & 7;
    uint32_t smb = smem_u32(sm);
    uint32_t aB  = smb + P_AS + (uint32_t)((mg2 * 16 + rin + (grp & 1) * 8) * P_ROW + (grp >> 1) * 16);
    uint32_t bB0 = smb + P_BS + (uint32_t)((ng * 16 + rin) * P_ROW + grp * 16);

    float acc[2][4];
#pragma unroll
    for (int t = 0; t < 2; t++)
#pragma unroll
        for (int q = 0; q < 4; q++) acc[t][q] = 0.f;

#pragma unroll
    for (int c = 0; c < 4; c++) {
        uint32_t Af[4][4];
#pragma unroll
        for (int ks = 0; ks < 4; ks++) ldsm_x4(Af[ks], aB + c * 128 + ks * 32);
#pragma unroll
        for (int t = 0; t < 2; t++) {
            uint32_t bf[8];
            uint32_t bB = bB0 + (uint32_t)(t * 8 * P_ROW + c * 128);
#pragma unroll
            for (int kp = 0; kp < 2; kp++) ldsm_x4(&bf[kp * 4], bB + kp * 64);
#pragma unroll
            for (int ks = 0; ks < 4; ks++)
                mma_fp16(acc[t], Af[ks], bf[ks * 2], bf[ks * 2 + 1]);
        }
    }

    // ---- epilogue: partial slab, [ma][o] layout, float2 stores ----
    float* dst = g_P[s];
    int ma_r = ma0 + mg2 * 16 + (l >> 2);
    int o_c  = ob0 + ng * 16 + (l & 3) * 2;
#pragma unroll
    for (int t = 0; t < 2; t++) {
        *(float2*)&dst[ma_r * 64 + o_c + t * 8]       = make_float2(acc[t][0], acc[t][1]);
        *(float2*)&dst[(ma_r + 8) * 64 + o_c + t * 8] = make_float2(acc[t][2], acc[t][3]);
    }
}

// ---------------------------------------------------------------------------
// Kernel 2: reduce split-K partials, *C_RELAX, fp16-cast, pack into main's
// B-fragment order. Loads lane-coalesced over o.
// ---------------------------------------------------------------------------
__global__ __launch_bounds__(256) void reduce_kernel() {
    int e = blockIdx.x * 256 + threadIdx.x;   // 0..16383
    int o = e & 63;
    int j = e >> 6;                           // k-pair index (k = 2j over ma)

    float s0 = 0.f, s1 = 0.f;
#pragma unroll
    for (int s = 0; s < NSLICE; s++) {
        s0 += g_P[s][(2 * j) * 64 + o];
        s1 += g_P[s][(2 * j + 1) * 64 + o];
    }
    uint32_t h = h2pack(s0 * C_RELAX, s1 * C_RELAX);

    int k   = 2 * j;
    int n   = o;
    int i   = k >> 6;                 // chunk
    int r   = k & 63;
    int ks  = r >> 4;
    int rem = r & 15;                 // even
    int cc  = rem >> 2;               // lane's c
    int comp = (ks & 1) * 2 + ((rem & 2) >> 1);
    int kp  = ks >> 1;
    int nt  = n >> 3;
    int lI  = ((n & 7) << 2) | cc;

    ((uint32_t*)g_Bpk)[((((i * 8 + nt) * 2 + kp) * 32) + lI) * 4 + comp] = h;
}

// ---------------------------------------------------------------------------
// Kernel 3: main GEMM, fragment-direct, barrier-free, software-pipelined.
//   out(8192,64) = X(8192,512) @ A(512,64)
// 512 warps (256 blocks x 2): warp = 16 rows x 64 cols, K=512 in 8 chunks.
// Chunk i+1's X loads are issued BEFORE chunk i's 32 MMAs -> DRAM latency
// hidden behind tensor work. B-frags from g_Bpk (64 KB, L1-hot).
// ---------------------------------------------------------------------------
__global__ __launch_bounds__(64, 1) void main_kernel(
        const float* __restrict__ X, float* __restrict__ out) {
    int W = blockIdx.x * 2 + (threadIdx.x >> 5);
    int l = threadIdx.x & 31;
    int c = l & 3, rY = l >> 2;
    int r0 = W * 16;

    float acc[8][4];
#pragma unroll
    for (int nt = 0; nt < 8; nt++)
#pragma unroll
        for (int q = 0; q < 4; q++) acc[nt][q] = 0.f;

    const float* x0 = X + (r0 + rY) * 512 + 4 * c;
    const float* x1 = x0 + 8 * 512;

    // prologue: chunk 0 loads
    float4 lo[4], hi[4];
#pragma unroll
    for (int ks = 0; ks < 4; ks++) {
        lo[ks] = *(const float4*)(x0 + ks * 16);
        hi[ks] = *(const float4*)(x1 + ks * 16);
    }

#pragma unroll
    for (int i = 0; i < 8; i++) {
        // convert current chunk to A-frags
        uint32_t A[4][4];
#pragma unroll
        for (int ks = 0; ks < 4; ks++) {
            A[ks][0] = h2pack(lo[ks].x, lo[ks].y);
            A[ks][1] = h2pack(hi[ks].x, hi[ks].y);
            A[ks][2] = h2pack(lo[ks].z, lo[ks].w);
            A[ks][3] = h2pack(hi[ks].z, hi[ks].w);
        }
        // issue next chunk's loads before the MMA block
        if (i < 7) {
            int k0 = (i + 1) * 64;
#pragma unroll
            for (int ks = 0; ks < 4; ks++) {
                lo[ks] = *(const float4*)(x0 + k0 + ks * 16);
                hi[ks] = *(const float4*)(x1 + k0 + ks * 16);
            }
        }
        // 32 MMAs for this chunk
#pragma unroll
        for (int nt = 0; nt < 8; nt++) {
#pragma unroll
            for (int kp = 0; kp < 2; kp++) {
                uint4 b = g_Bpk[((i * 8 + nt) * 2 + kp) * 32 + l];
                mma_fp16(acc[nt], A[2 * kp],     b.x, b.y);
                mma_fp16(acc[nt], A[2 * kp + 1], b.z, b.w);
            }
        }
    }

    int rr = r0 + rY;
    int cb = 2 * c;
#pragma unroll
    for (int nt = 0; nt < 8; nt++) {
        *(float2*)&out[rr * 64 + nt * 8 + cb]       = make_float2(acc[nt][0], acc[nt][1]);
        *(float2*)&out[(rr + 8) * 64 + nt * 8 + cb] = make_float2(acc[nt][2], acc[nt][3]);
    }
}

// ---------------------------------------------------------------------------
extern "C" void kernel_launch(void* const* d_in, const int* in_sizes, int n_in,
                              void* d_out, int out_size) {
    const float* x    = (const float*)d_in[0];   // (8192, 512)
    const float* Win  = (const float*)d_in[1];   // (512h, 512mb)
    const float* Wout = (const float*)d_in[2];   // (64, 4096)
    float* out        = (float*)d_out;           // (8192, 64)

    cudaFuncSetAttribute(prep_gemm_kernel,
                         cudaFuncAttributeMaxDynamicSharedMemorySize, PREP_SMEM);

    prep_gemm_kernel<<<dim3(8, 2, NSLICE), 256, PREP_SMEM>>>(Win, Wout);
    reduce_kernel<<<64, 256>>>();
    main_kernel<<<256, 64>>>(x, out);
}